// round 7
// baseline (speedup 1.0000x reference)
#include <cuda_runtime.h>

// Geometry fixed by the reference: (2,1,192,192,192) fp32 x3 -> scalar
constexpr int BATCH = 2, D = 192, H = 192, W = 192;
constexpr int DS = H * W;
constexpr int XV = 4;                  // x-values per pair (one float4)
constexpr int ZC = 24;                 // z planes per pair
constexpr int GX = W / XV;             // 48
constexpr int NZ = D / ZC;             // 8
constexpr int THREADS = 128;
constexpr long long NVOX = (long long)BATCH * D * H * W;
constexpr int NPAIRS  = GX * H * NZ * BATCH;       // 147456
constexpr int NBLOCKS = NPAIRS * 2 / THREADS;      // 2304

__device__ double   g_accum = 0.0;
__device__ unsigned g_done  = 0;

__device__ __forceinline__ float fsqrt_a(float x) {
    float y; asm("sqrt.approx.f32 %0, %1;" : "=f"(y) : "f"(x)); return y;
}
__device__ __forceinline__ float htanh(float x) {
    float y; asm("tanh.approx.f32 %0, %1;" : "=f"(y) : "f"(x)); return y;
}

struct Fresh { float A[XV], Bx[XV], By[XV], C[XV]; };   // C = raw center row
// Streaming z-partials for ONE image (24 regs):
//   Am/Ac = A[c-1], A[c];  Ux/Cx = Bx[c-1]+2Bx[c], Bx[c];  Uy/Cy likewise.
struct State { float Am[XV], Ac[XV], Ux[XV], Cx[XV], Uy[XV], Cy[XV]; };

// x-pass for one row: s = [1,2,1]*x, d = x[+1]-x[-1], zero-padded OOB.
__device__ __forceinline__ void row_sd(const float* __restrict__ p, bool ok, bool xl, bool xr,
                                       float s[XV], float d[XV], float* cen) {
    float v0 = 0.f, v1 = 0.f, v2 = 0.f, v3 = 0.f, vm = 0.f, vp = 0.f;
    if (ok) {
        float4 c = __ldg(reinterpret_cast<const float4*>(p));
        v0 = c.x; v1 = c.y; v2 = c.z; v3 = c.w;
        if (xl) vm = __ldg(p - 1);
        if (xr) vp = __ldg(p + XV);
    }
    s[0] = fmaf(2.f, v0, vm + v1);
    s[1] = fmaf(2.f, v1, v0 + v2);
    s[2] = fmaf(2.f, v2, v1 + v3);
    s[3] = fmaf(2.f, v3, v2 + vp);
    d[0] = v1 - vm;
    d[1] = v2 - v0;
    d[2] = v3 - v1;
    d[3] = vp - v2;
    if (cen) { cen[0] = v0; cen[1] = v1; cen[2] = v2; cen[3] = v3; }
}

// In-plane separable pass: fold rows (gy-1, gy, gy+1) of the plane whose
// center row is at pc.  A = sy(sx), By = dy(sx), Bx = sy(dx).
__device__ __forceinline__ Fresh plane_pass(const float* __restrict__ pc, bool zok,
                                            bool ymok, bool ypok, bool xl, bool xr) {
    float sa[XV], da[XV], sb[XV], db[XV], sc[XV], dc[XV];
    Fresh f;
    row_sd(pc - W, zok && ymok, xl, xr, sa, da, nullptr);
    row_sd(pc,     zok,         xl, xr, sb, db, f.C);
    row_sd(pc + W, zok && ypok, xl, xr, sc, dc, nullptr);
#pragma unroll
    for (int j = 0; j < XV; j++) {
        f.A[j]  = fmaf(2.f, sb[j], sa[j] + sc[j]);
        f.By[j] = sa[j] - sc[j];
        f.Bx[j] = fmaf(2.f, db[j], da[j] + dc[j]);
    }
    return f;
}

__device__ __forceinline__ void state_init(State& s, const Fresh& fm1, const Fresh& f0) {
#pragma unroll
    for (int j = 0; j < XV; j++) {
        s.Am[j] = fm1.A[j];  s.Ac[j] = f0.A[j];
        s.Ux[j] = fmaf(2.f, f0.Bx[j], fm1.Bx[j]);  s.Cx[j] = f0.Bx[j];
        s.Uy[j] = fmaf(2.f, f0.By[j], fm1.By[j]);  s.Cy[j] = f0.By[j];
    }
}

// z-combine at plane c given fresh plane c+1; advances streaming state.
__device__ __forceinline__ void step_img(State& s, const Fresh& f, float msq[XV]) {
#pragma unroll
    for (int j = 0; j < XV; j++) {
        float gx = s.Ux[j] + f.Bx[j];
        float gy = s.Uy[j] + f.By[j];
        float gz = s.Am[j] - f.A[j];
        msq[j] = fmaf(gx, gx, fmaf(gy, gy, fmaf(gz, gz, 1e-10f)));
        s.Ux[j] = fmaf(2.f, f.Bx[j], s.Cx[j]);  s.Cx[j] = f.Bx[j];
        s.Uy[j] = fmaf(2.f, f.By[j], s.Cy[j]);  s.Cy[j] = f.By[j];
        s.Am[j] = s.Ac[j];                      s.Ac[j] = f.A[j];
    }
}

__global__ void __launch_bounds__(THREADS, 7)
k_loss(const float* __restrict__ pred,
       const float* __restrict__ gt,
       const float* __restrict__ mask,
       float* __restrict__ out) {
    const int gtid = blockIdx.x * THREADS + threadIdx.x;
    const int im = gtid & 1;          // 0: lane owns pred, 1: lane owns gt
    const int pr = gtid >> 1;         // pair index
    int xg  = pr % GX;
    int tq  = pr / GX;
    int gy  = tq % H;  tq /= H;
    int zc  = tq % NZ;
    int b   = tq / NZ;
    const int x0 = xg * XV, z0 = zc * ZC;

    const bool ymok = (gy > 0), ypok = (gy < H - 1);
    const bool xl = (x0 > 0), xr = (x0 + XV < W);

    const float* ownBase = im ? gt : pred;
    const float* othBase = im ? pred : gt;
    const size_t cell = (size_t)b * D * DS + (size_t)gy * W + x0;

    const float* pI = ownBase + cell + (long long)(z0 - 1) * DS;  // own stencil walker
    const float* pO = othBase + cell + (long long)z0 * DS;        // other-image center
    const float* pM = mask    + cell + (long long)z0 * DS;        // mask center

    // Prologue: own image, planes z0-1 and z0
    Fresh fm1 = plane_pass(pI, z0 > 0, ymok, ypok, xl, xr);
    pI += DS;
    Fresh f0  = plane_pass(pI, true,  ymok, ypok, xl, xr);
    State st;
    state_init(st, fm1, f0);
    float cen[XV];                      // own raw centers at plane c
#pragma unroll
    for (int j = 0; j < XV; j++) cen[j] = f0.C[j];

    float acc = 0.f;
#pragma unroll 2
    for (int c = z0; c < z0 + ZC; c++) {
        pI += DS;                                  // own image, plane c+1
        Fresh f = plane_pass(pI, c + 1 < D, ymok, ypok, xl, xr);

        float msq[XV];
        step_img(st, f, msq);

        float mag[XV], omag[XV];
#pragma unroll
        for (int j = 0; j < XV; j++) mag[j] = fsqrt_a(msq[j]);
#pragma unroll
        for (int j = 0; j < XV; j++) omag[j] = __shfl_xor_sync(0xffffffffu, mag[j], 1);

        // other-image center (partner loaded it -> L1 hit) and mask
        float4 ov4 = __ldg(reinterpret_cast<const float4*>(pO));
        float4 mv4 = __ldg(reinterpret_cast<const float4*>(pM));
        pO += DS; pM += DS;

        const float othv[XV] = { ov4.x, ov4.y, ov4.z, ov4.w };
        const float mv[XV]   = { mv4.x, mv4.y, mv4.z, mv4.w };

        // Both lanes compute the identical full 4-wide loss (signs cancel
        // under squaring); scale by 0.5 so the pair contributes it once.
#pragma unroll
        for (int j = 0; j < XV; j++) {
            float d   = cen[j] - othv[j];
            float mse = d * d * mv[j];
            float dm  = mag[j] - omag[j];
            float mge = dm * dm * mv[j];
            acc += 0.5f * fmaf(htanh(mge), mse, mse);
        }

#pragma unroll
        for (int j = 0; j < XV; j++) cen[j] = f.C[j];   // centers for next plane
    }

    // Block reduction -> one fp64 atomic; last block finalizes + re-arms
#pragma unroll
    for (int o = 16; o; o >>= 1) acc += __shfl_xor_sync(0xffffffffu, acc, o);
    __shared__ float ws[THREADS / 32];
    int lane = threadIdx.x & 31, wid = threadIdx.x >> 5;
    if (lane == 0) ws[wid] = acc;
    __syncthreads();
    if (threadIdx.x == 0) {
        float s = ws[0] + ws[1] + ws[2] + ws[3];
        atomicAdd(&g_accum, (double)s);
        __threadfence();
        unsigned tk = atomicAdd(&g_done, 1u);
        if (tk == (unsigned)gridDim.x - 1u) {
            double total = atomicAdd(&g_accum, 0.0);
            out[0] = (float)(total / (double)NVOX);
            g_accum = 0.0;
            g_done  = 0;
        }
    }
}

extern "C" void kernel_launch(void* const* d_in, const int* in_sizes, int n_in,
                              void* d_out, int out_size) {
    k_loss<<<NBLOCKS, THREADS>>>((const float*)d_in[0], (const float*)d_in[1],
                                 (const float*)d_in[2], (float*)d_out);
}